// round 9
// baseline (speedup 1.0000x reference)
#include <cuda_runtime.h>

// ATCA/TCA loss, C=10, T=500, N=128, B=256.
// 8 chunk-warps x 32 neurons per block (chunk L=63). Per tile: 4x LDG.128 ->
// 4x STS.128 -> batched LDS.32 into a register window. Scan state minimized:
// single last-spike index `ls` drives both cluster-start and m0 gates with
// compile-time immediates; connectivity is a local flag (no time compare).

#define NEGF (-3.0e30f)

__global__ void atca_zero(float* out) { out[0] = 0.0f; }

#define INS4(x) do { float _x = (x); \
    float _a0 = fmaxf(t40, _x), _b0 = fminf(t40, _x); \
    float _a1 = fmaxf(t41, _b0), _b1 = fminf(t41, _b0); \
    float _a2 = fmaxf(t42, _b1), _b2 = fminf(t42, _b1); \
    t43 = fmaxf(t43, _b2); t42 = _a2; t41 = _a1; t40 = _a0; } while (0)

// load tile j (16 rows x 32 neurons): rows 16j + (lane>>3) + {0,4,8,12}
#define LOADT(j, guarded) do { \
    const int _r0 = (j) * 16 + (lane >> 3); \
    const float4* _ap = (const float4*)(gp + (size_t)_r0 * 128) + (lane & 7); \
    if (!(guarded)) { \
        P0 = __ldg(_ap); \
        P1 = __ldg(_ap + 4 * 32); \
        P2 = __ldg(_ap + 8 * 32); \
        P3 = __ldg(_ap + 12 * 32); \
    } else { \
        const float4 _ng = make_float4(NEGF, NEGF, NEGF, NEGF); \
        P0 = (t0 + _r0      < 500) ? __ldg(_ap)           : _ng; \
        P1 = (t0 + _r0 + 4  < 500) ? __ldg(_ap + 4 * 32)  : _ng; \
        P2 = (t0 + _r0 + 8  < 500) ? __ldg(_ap + 8 * 32)  : _ng; \
        P3 = (t0 + _r0 + 12 < 500) ? __ldg(_ap + 12 * 32) : _ng; \
    } } while (0)

__global__ void __launch_bounds__(256)
atca9(const float* __restrict__ vmem, const int* __restrict__ labels,
      float* __restrict__ out)
{
    __shared__ __align__(16) float sbuf[8][512];      // [warp][16*32]
    __shared__ int   s_ns[8][32], s_cn[8][32];
    __shared__ float s_c0[8][32], s_lm[8][32], s_mid[8][32];
    __shared__ float s_msum[8][32], s_m0[8][32];

    const int lane = threadIdx.x & 31;
    const int c    = threadIdx.x >> 5;          // chunk = warp id (0..7)
    const int nb   = blockIdx.x * 32;           // 32-aligned neuron base
    const int b    = nb >> 7;
    const int n0   = nb & 127;
    const int neuron = nb + lane;
    const int t0   = c * 63;                    // chunk owns [t0, t0+63)
    const float* __restrict__ gp = vmem + ((size_t)b * 500 + t0) * 128 + n0;
    const float* __restrict__ p  = gp + lane;

    // ---- left halo: last spike in [t0-10, t0), k-relative ----
    int hl = -1000;
    if (c != 0) {
        #pragma unroll
        for (int h = 0; h < 10; ++h) {
            const float v = __ldg(p + (h - 10) * 128);
            if (v >= 0.0f) hl = h - 10;
        }
    }
    int   ls = hl;              // last spike index (k-relative, incl. halo)
    int   ns = 0;               // global cluster starts within this chunk
    bool  conn = false;         // first spike connected to previous chunk
    bool  seen = false;
    float c0v = NEGF;           // seg0 (connected prefix) max
    float cm  = NEGF;           // current segment max
    float mid0 = NEGF;          // largest fully-retired cluster max
    float msum = 0.0f;          // sum of fully-retired cluster maxima
    float m0 = NEGF;            // max over unmasked own times

    float A[16], Bb[16];
    float4 P0, P1, P2, P3;
    LOADT(0, false);                            // prologue (always in-bounds)

    #pragma unroll
    for (int j = 0; j < 5; ++j) {
        float*       cur = (j & 1) ? Bb : A;
        const float* prv = (j & 1) ? A : Bb;

        __syncwarp();                           // prior tile's LDS done
        float4* bp = (float4*)sbuf[c];
        bp[0 * 32 + lane] = P0;
        bp[1 * 32 + lane] = P1;
        bp[2 * 32 + lane] = P2;
        bp[3 * 32 + lane] = P3;
        if (j < 4) { LOADT(j + 1, (c == 7) && (j + 1 >= 3)); }
        __syncwarp();

        const float* sb = sbuf[c];
        #pragma unroll
        for (int k = 0; k < 16; ++k) {
            if (16 * j + k <= 72) cur[k] = sb[k * 32 + lane];
        }
        #pragma unroll
        for (int k = 0; k < 16; ++k) {
            const int kk = 16 * j + k;          // compile-time
            if (kk > 72) continue;
            const float v = cur[k];
            const bool spk  = (v >= 0.0f);
            const bool newp = spk && (ls < kk - 10);   // global cluster start
            if (kk < 10) {                      // connectivity decidable here only
                conn = conn || (spk && !seen && !newp);
                seen = seen || spk;
            }
            if (kk < 63) {                      // own piece range
                const bool pm  = newp && (ns >= 1);    // retire full cluster
                const bool pmf = newp && (ns == 0);    // retire seg0 -> c0
                msum += pm ? cm : 0.0f;
                mid0  = pm ? fmaxf(mid0, cm) : mid0;
                c0v   = pmf ? cm : c0v;
                const float cmx = fmaxf(cm, v);
                cm = newp ? v : (spk ? cmx : cm);
                ns += newp ? 1 : 0;
            }
            ls = spk ? kk : ls;                 // incl. overhang spikes
            if (kk >= 10) {                     // m0 for s = kk-10
                const float vl = (k >= 10) ? cur[k - 10] : prv[k + 6];
                if (ls < kk - 20) m0 = fmaxf(m0, vl);
            }
        }
    }

    // ---- publish chunk state ----
    s_ns[c][lane]   = ns;
    s_cn[c][lane]   = conn ? 1 : 0;
    s_c0[c][lane]   = c0v;
    s_lm[c][lane]   = cm;                       // open segment max at end
    s_mid[c][lane]  = mid0;
    s_msum[c][lane] = msum;
    s_m0[c][lane]   = m0;
    __syncthreads();

    if (c == 0) {
        float m0g = NEGF;
        #pragma unroll
        for (int cc = 0; cc < 8; ++cc) m0g = fmaxf(m0g, s_m0[cc][lane]);

        int nc = 0; float tot = 0.0f;
        float t40 = NEGF, t41 = NEGF, t42 = NEGF, t43 = NEGF;
        bool ov = false, valid = false;
        float open = NEGF;
        #pragma unroll
        for (int cc = 0; cc < 8; ++cc) {
            const int   nsc = s_ns[cc][lane];
            const bool  cn  = s_cn[cc][lane] != 0;
            const float lmx = s_lm[cc][lane];
            if (nsc == 0) {
                // all spikes (if any) connected -> extend chain; NEGF is a no-op
                open = fmaxf(open, lmx);
            } else {
                if (cn) {
                    const float fc = fmaxf(open, s_c0[cc][lane]);
                    ++nc; tot += fc; INS4(fc);          // chain + seg0 closes
                } else if (valid) {
                    ++nc; tot += open; INS4(open);      // prev chain closes
                }
                const int mc = nsc - 1;                 // fully-retired clusters
                nc += mc; tot += s_msum[cc][lane];
                if (mc >= 1) INS4(s_mid[cc][lane]);
                if (mc >= 2) ov = true;                 // top-4 may be inexact
                open = lmx; valid = true;
            }
        }
        if (valid) { ++nc; tot += open; INS4(open); }
        const float vmg = t40;   // max cluster max == global max when nc >= 1

        float contrib = 0.0f;
        const int label = labels[neuron];
        if (label > nc) {
            const bool any_un = (m0g > -1.0e29f);
            if (!any_un) {
                contrib = vmg;                  // full0 => spikes exist => t40 valid
            } else {
                float m_rest;
                if (nc > 0) {
                    m_rest = m0g;     // argmax is a spike -> mask2 == mask
                } else {
                    int tm = 0; float vm = NEGF;   // cold: no spikes at all
                    for (int t = 0; t < 500; ++t) {
                        const float v = __ldg(p + t * 128);
                        if (v > vm) { vm = v; tm = t; }
                    }
                    float v2 = NEGF;
                    for (int t = 0; t < 500; ++t)
                        if (t < tm - 5 || t > tm + 5)
                            v2 = fmaxf(v2, __ldg(p + t * 128));
                    const bool full2 = (tm <= 5) && (tm + 5 >= 499);
                    m_rest = full2 ? vm : v2;
                }
                const float dE = (float)(label - nc);
                contrib = -((m0g + (dE - 1.0f) * m_rest) / dE);
            }
        } else if (label < nc) {
            if (ov && label >= 1) {
                // rare exact top-4 recompute (serial rescan; t0 == 0 here)
                t40 = t41 = t42 = t43 = NEGF;
                int last = -1000; float cmx = NEGF; bool open2 = false;
                for (int t = 0; t < 500; ++t) {
                    const float v = __ldg(p + t * 128);
                    if (v >= 0.0f) {
                        if (t - last > 10) {
                            if (open2) INS4(cmx);
                            cmx = v; open2 = true;
                        } else cmx = fmaxf(cmx, v);
                        last = t;
                    }
                }
                if (open2) INS4(cmx);
            }
            float s = tot;                      // sum of (nc-label) smallest
            if (label >= 1) s -= t40;
            if (label >= 2) s -= t41;
            if (label >= 3) s -= t42;
            if (label >= 4) s -= t43;
            contrib = s / (float)(nc - label);
        }
        out[1 + neuron] = (float)nc;            // coalesced store

        float val = contrib;
        #pragma unroll
        for (int off = 16; off > 0; off >>= 1)
            val += __shfl_down_sync(0xffffffffu, val, off);
        if (lane == 0) atomicAdd(out, val);
    }
}

extern "C" void kernel_launch(void* const* d_in, const int* in_sizes, int n_in,
                              void* d_out, int out_size) {
    const float* vmem   = (const float*)d_in[0];
    const int*   labels = (const int*)d_in[2];
    float* out = (float*)d_out;

    atca_zero<<<1, 1>>>(out);
    // 32768 neurons / 32 per block = 1024 blocks of 256 (8 chunk-warps)
    atca9<<<1024, 256>>>(vmem, labels, out);
}

// round 11
// speedup vs baseline: 2.8711x; 2.8711x over previous
#include <cuda_runtime.h>

// ATCA/TCA loss, C=10, T=500, N=128, B=256.
// 8 chunk-warps x 32 neurons per block (chunk L=63). Staging via cp.async.cg
// into a 3-buffer smem ring (depth-2 pipeline); scan body identical to the
// R8 kernel (known-good codegen).

#define NEGF (-3.0e30f)

__global__ void atca_zero(float* out) { out[0] = 0.0f; }

#define INS4(x) do { float _x = (x); \
    float _a0 = fmaxf(t40, _x), _b0 = fminf(t40, _x); \
    float _a1 = fmaxf(t41, _b0), _b1 = fminf(t41, _b0); \
    float _a2 = fmaxf(t42, _b1), _b2 = fminf(t42, _b1); \
    t43 = fmaxf(t43, _b2); t42 = _a2; t41 = _a1; t40 = _a0; } while (0)

#define CPA16(dst, src) \
    asm volatile("cp.async.cg.shared.global [%0], [%1], 16;\n" \
                 :: "r"(dst), "l"(src) : "memory")
#define CPA_COMMIT()  asm volatile("cp.async.commit_group;\n" ::: "memory")
#define CPA_WAIT(n)   asm volatile("cp.async.wait_group %0;\n" :: "n"(n) : "memory")

// async-copy tile j (16 rows x 32 neurons) into ring buffer bi.
// rows r = 16j + (lane>>3) + {0,4,8,12}; each lane moves 4 x 16B.
#define CPTILE(j, bi, guarded) do { \
    const int _r0 = (j) * 16 + (lane >> 3); \
    const float* _sp = gp + (size_t)_r0 * 128 + (lane & 7) * 4; \
    const unsigned _d0 = sb_addr + (bi) * 2048u + ((unsigned)lane << 4); \
    if (!(guarded)) { \
        CPA16(_d0,        _sp); \
        CPA16(_d0 + 512,  _sp + 4 * 128); \
        CPA16(_d0 + 1024, _sp + 8 * 128); \
        CPA16(_d0 + 1536, _sp + 12 * 128); \
    } else { \
        if (t0 + _r0      < 500) CPA16(_d0,        _sp); \
        if (t0 + _r0 + 4  < 500) CPA16(_d0 + 512,  _sp + 4 * 128); \
        if (t0 + _r0 + 8  < 500) CPA16(_d0 + 1024, _sp + 8 * 128); \
        if (t0 + _r0 + 12 < 500) CPA16(_d0 + 1536, _sp + 12 * 128); \
    } \
    CPA_COMMIT(); \
} while (0)

__global__ void __launch_bounds__(256)
atca10(const float* __restrict__ vmem, const int* __restrict__ labels,
       float* __restrict__ out)
{
    // 8 warps x 3 ring buffers x 2KB = 48KB (static cap). After the scan,
    // each warp overlays its 9x32-float publish block onto its buffer 0.
    __shared__ __align__(16) float sbuf[8][3][512];

    const int lane = threadIdx.x & 31;
    const int c    = threadIdx.x >> 5;          // chunk = warp id (0..7)
    const int nb   = blockIdx.x * 32;           // 32-aligned neuron base
    const int b    = nb >> 7;
    const int n0   = nb & 127;
    const int neuron = nb + lane;
    const int t0   = c * 63;                    // chunk owns [t0, t0+63)
    const float* __restrict__ gp = vmem + ((size_t)b * 500 + t0) * 128 + n0;
    const float* __restrict__ p  = gp + lane;

    const unsigned sb_addr =
        (unsigned)__cvta_generic_to_shared(&sbuf[c][0][0]);

    // ---- left halo: last spike in [t0-10, t0) ----
    int hl = -1000;
    if (c != 0) {
        #pragma unroll
        for (int h = 0; h < 10; ++h) {
            const float v = __ldg(p + (h - 10) * 128);
            if (v >= 0.0f) hl = h - 10;
        }
    }
    int   relB = hl + 20;       // s=kk-10 unmasked iff kk > relB
    int   rel  = -1000;         // new piece iff spike && kk > rel
    int   ns   = 0;
    int   tfk  = 100000;        // first-piece k (relevant iff < 10)
    int   tlk  = -100000;       // last-spike k (relevant iff >= 53)
    float fm = NEGF, cm = NEGF;
    float mid0 = NEGF, msum = 0.0f;
    float m0 = NEGF, vmax = NEGF;

    float A[16], Bb[16];

    // prologue: tiles 0 and 1 in flight (always fully in-bounds)
    CPTILE(0, 0, false);
    CPTILE(1, 1, false);

    #pragma unroll
    for (int j = 0; j < 5; ++j) {
        float*       cur = (j & 1) ? Bb : A;
        const float* prv = (j & 1) ? A : Bb;

        if (j < 4) { CPA_WAIT(1); } else { CPA_WAIT(0); }   // tile j landed
        __syncwarp();

        // batched LDS into register window (c==7: rows beyond t=499 -> NEGF)
        const float* sb = sbuf[c][j % 3];
        #pragma unroll
        for (int k = 0; k < 16; ++k) {
            const int kk = 16 * j + k;
            if (kk > 72) continue;
            if (kk <= 58) cur[k] = sb[k * 32 + lane];
            else          cur[k] = (c != 7) ? sb[k * 32 + lane] : NEGF;
        }
        __syncwarp();                            // all lanes' LDS done
        if (j + 2 <= 4) { CPTILE(j + 2, (j + 2) % 3, (c == 7) && (j + 2 >= 3)); }

        #pragma unroll
        for (int k = 0; k < 16; ++k) {
            const int kk = 16 * j + k;          // compile-time
            if (kk > 72) continue;
            const float v = cur[k];
            const bool spk = (v >= 0.0f);
            relB = spk ? kk + 20 : relB;
            if (kk >= 10) {                     // m0 for s = kk-10 (own range)
                const float vl = (k >= 10) ? cur[k - 10] : prv[k + 6];
                if (kk > relB) m0 = fmaxf(m0, vl);
            }
            if (kk < 63) {                      // own piece range
                vmax = fmaxf(vmax, v);
                const bool newp = spk && (kk > rel);
                const bool was0 = (ns == 0);
                const bool was1 = (ns == 1);
                const bool ge2  = (ns >= 2);
                fm = (newp && was1) ? cm : fm;
                const bool pm = newp && ge2;    // retire an interior piece
                msum += pm ? cm : 0.0f;
                mid0  = pm ? fmaxf(mid0, cm) : mid0;
                const float cm1 = fmaxf(cm, v);
                cm = newp ? v : (spk ? cm1 : cm);
                ns += newp ? 1 : 0;
                if (kk < 10)  tfk = (newp && was0) ? kk : tfk;
                if (kk >= 53) tlk = spk ? kk : tlk;
                rel = spk ? kk + 10 : rel;
            }
        }
    }
    const float lm = cm;
    if (ns == 1) fm = cm;

    // ---- publish chunk state (overlay onto own ring buffer 0) ----
    float* pub = sbuf[c][0];
    pub[0 * 32 + lane] = __int_as_float(ns);
    pub[1 * 32 + lane] = __int_as_float(t0 + tfk);
    pub[2 * 32 + lane] = __int_as_float(t0 + tlk);
    pub[3 * 32 + lane] = fm;
    pub[4 * 32 + lane] = lm;
    pub[5 * 32 + lane] = mid0;
    pub[6 * 32 + lane] = msum;
    pub[7 * 32 + lane] = m0;
    pub[8 * 32 + lane] = vmax;
    __syncthreads();

    if (c == 0) {
        float m0g = NEGF, vmg = NEGF;
        #pragma unroll
        for (int cc = 0; cc < 8; ++cc) {
            m0g = fmaxf(m0g, sbuf[cc][0][7 * 32 + lane]);
            vmg = fmaxf(vmg, sbuf[cc][0][8 * 32 + lane]);
        }

        int nc = 0; float tot = 0.0f;
        float t40 = NEGF, t41 = NEGF, t42 = NEGF, t43 = NEGF;
        bool ov = false, valid = false;
        float open = NEGF; int last_t = -100000;
        #pragma unroll
        for (int cc = 0; cc < 8; ++cc) {
            const float* pc = sbuf[cc][0];
            const int nsc = __float_as_int(pc[0 * 32 + lane]);
            if (nsc == 0) continue;             // spike-free chunk
            const bool conn = (__float_as_int(pc[1 * 32 + lane]) - last_t) <= 10;
            if (conn) {
                open = fmaxf(open, pc[3 * 32 + lane]);
            } else {
                if (valid) { ++nc; tot += open; INS4(open); }
                open = pc[3 * 32 + lane]; valid = true;
            }
            if (nsc >= 2) {
                ++nc; tot += open; INS4(open);  // chain closes inside chunk
                const int mc = nsc - 2;         // interior pieces
                nc += mc; tot += pc[6 * 32 + lane];
                if (mc >= 1) INS4(pc[5 * 32 + lane]);
                if (mc >= 2) ov = true;         // top-4 may be inexact
                open = pc[4 * 32 + lane]; valid = true;
            }
            last_t = __float_as_int(pc[2 * 32 + lane]);
        }
        if (valid) { ++nc; tot += open; INS4(open); }

        float contrib = 0.0f;
        const int label = labels[neuron];
        if (label > nc) {
            const bool any_un = (m0g > -1.0e29f);
            if (!any_un) {
                contrib = vmg;                  // full0: everything masked
            } else {
                float m_rest;
                if (nc > 0) {
                    m_rest = m0g;     // argmax is a spike -> mask2 == mask
                } else {
                    int tm = 0; float vm = NEGF;   // cold: no spikes at all
                    for (int t = 0; t < 500; ++t) {
                        const float v = __ldg(p + t * 128);
                        if (v > vm) { vm = v; tm = t; }
                    }
                    float v2 = NEGF;
                    for (int t = 0; t < 500; ++t)
                        if (t < tm - 5 || t > tm + 5)
                            v2 = fmaxf(v2, __ldg(p + t * 128));
                    const bool full2 = (tm <= 5) && (tm + 5 >= 499);
                    m_rest = full2 ? vmg : v2;
                }
                const float dE = (float)(label - nc);
                contrib = -((m0g + (dE - 1.0f) * m_rest) / dE);
            }
        } else if (label < nc) {
            if (ov && label >= 1) {
                // rare exact top-4 recompute (serial rescan; t0 == 0 here)
                t40 = t41 = t42 = t43 = NEGF;
                int last = -1000; float cmx = NEGF; bool open2 = false;
                for (int t = 0; t < 500; ++t) {
                    const float v = __ldg(p + t * 128);
                    if (v >= 0.0f) {
                        if (t - last > 10) {
                            if (open2) INS4(cmx);
                            cmx = v; open2 = true;
                        } else cmx = fmaxf(cmx, v);
                        last = t;
                    }
                }
                if (open2) INS4(cmx);
            }
            float s = tot;                      // sum of (nc-label) smallest
            if (label >= 1) s -= t40;
            if (label >= 2) s -= t41;
            if (label >= 3) s -= t42;
            if (label >= 4) s -= t43;
            contrib = s / (float)(nc - label);
        }
        out[1 + neuron] = (float)nc;            // coalesced store

        float val = contrib;
        #pragma unroll
        for (int off = 16; off > 0; off >>= 1)
            val += __shfl_down_sync(0xffffffffu, val, off);
        if (lane == 0) atomicAdd(out, val);
    }
}

extern "C" void kernel_launch(void* const* d_in, const int* in_sizes, int n_in,
                              void* d_out, int out_size) {
    const float* vmem   = (const float*)d_in[0];
    const int*   labels = (const int*)d_in[2];
    float* out = (float*)d_out;

    atca_zero<<<1, 1>>>(out);
    // 32768 neurons / 32 per block = 1024 blocks of 256 (8 chunk-warps)
    atca10<<<1024, 256>>>(vmem, labels, out);
}

// round 12
// speedup vs baseline: 3.1954x; 1.1130x over previous
#include <cuda_runtime.h>

// ATCA/TCA loss, C=10, T=500, N=128, B=256.
// R10 base (cp.async 3-buffer ring, 8 chunk-warps x 32 neurons, L=63) with
// three verified per-step trims: relB folded into rel for kk>=20, vmax
// tracking removed (== top cluster max when spikes exist), cm select removed.

#define NEGF (-3.0e30f)

__global__ void atca_zero(float* out) { out[0] = 0.0f; }

#define INS4(x) do { float _x = (x); \
    float _a0 = fmaxf(t40, _x), _b0 = fminf(t40, _x); \
    float _a1 = fmaxf(t41, _b0), _b1 = fminf(t41, _b0); \
    float _a2 = fmaxf(t42, _b1), _b2 = fminf(t42, _b1); \
    t43 = fmaxf(t43, _b2); t42 = _a2; t41 = _a1; t40 = _a0; } while (0)

#define CPA16(dst, src) \
    asm volatile("cp.async.cg.shared.global [%0], [%1], 16;\n" \
                 :: "r"(dst), "l"(src) : "memory")
#define CPA_COMMIT()  asm volatile("cp.async.commit_group;\n" ::: "memory")
#define CPA_WAIT(n)   asm volatile("cp.async.wait_group %0;\n" :: "n"(n) : "memory")

// async-copy tile j (16 rows x 32 neurons) into ring buffer bi.
#define CPTILE(j, bi, guarded) do { \
    const int _r0 = (j) * 16 + (lane >> 3); \
    const float* _sp = gp + (size_t)_r0 * 128 + (lane & 7) * 4; \
    const unsigned _d0 = sb_addr + (bi) * 2048u + ((unsigned)lane << 4); \
    if (!(guarded)) { \
        CPA16(_d0,        _sp); \
        CPA16(_d0 + 512,  _sp + 4 * 128); \
        CPA16(_d0 + 1024, _sp + 8 * 128); \
        CPA16(_d0 + 1536, _sp + 12 * 128); \
    } else { \
        if (t0 + _r0      < 500) CPA16(_d0,        _sp); \
        if (t0 + _r0 + 4  < 500) CPA16(_d0 + 512,  _sp + 4 * 128); \
        if (t0 + _r0 + 8  < 500) CPA16(_d0 + 1024, _sp + 8 * 128); \
        if (t0 + _r0 + 12 < 500) CPA16(_d0 + 1536, _sp + 12 * 128); \
    } \
    CPA_COMMIT(); \
} while (0)

__global__ void __launch_bounds__(256)
atca12(const float* __restrict__ vmem, const int* __restrict__ labels,
       float* __restrict__ out)
{
    // 8 warps x 3 ring buffers x 2KB = 48KB; publish block overlays buffer 0.
    __shared__ __align__(16) float sbuf[8][3][512];

    const int lane = threadIdx.x & 31;
    const int c    = threadIdx.x >> 5;          // chunk = warp id (0..7)
    const int nb   = blockIdx.x * 32;           // 32-aligned neuron base
    const int b    = nb >> 7;
    const int n0   = nb & 127;
    const int neuron = nb + lane;
    const int t0   = c * 63;                    // chunk owns [t0, t0+63)
    const float* __restrict__ gp = vmem + ((size_t)b * 500 + t0) * 128 + n0;
    const float* __restrict__ p  = gp + lane;

    const unsigned sb_addr =
        (unsigned)__cvta_generic_to_shared(&sbuf[c][0][0]);

    // ---- left halo: last spike in [t0-10, t0), k-relative ----
    int hl = -1000;
    if (c != 0) {
        #pragma unroll
        for (int h = 0; h < 10; ++h) {
            const float v = __ldg(p + (h - 10) * 128);
            if (v >= 0.0f) hl = h - 10;
        }
    }
    int   relB = hl + 20;       // mask gate for kk<20 (halo-aware)
    int   rel  = -1000;         // last local spike + 10; mask gate for kk>=20
    int   ns   = 0;
    int   tfk  = 100000;        // first-piece k (relevant iff < 10)
    int   tlk  = -100000;       // last-spike k (relevant iff >= 53)
    float fm = NEGF, cm = NEGF;
    float mid0 = NEGF, msum = 0.0f;
    float m0 = NEGF;

    float A[16], Bb[16];

    // prologue: tiles 0 and 1 in flight (always fully in-bounds)
    CPTILE(0, 0, false);
    CPTILE(1, 1, false);

    #pragma unroll
    for (int j = 0; j < 5; ++j) {
        float*       cur = (j & 1) ? Bb : A;
        const float* prv = (j & 1) ? A : Bb;

        if (j < 4) { CPA_WAIT(1); } else { CPA_WAIT(0); }   // tile j landed
        __syncwarp();

        // batched LDS into register window (c==7: rows beyond t=499 -> NEGF)
        const float* sb = sbuf[c][j % 3];
        #pragma unroll
        for (int k = 0; k < 16; ++k) {
            const int kk = 16 * j + k;
            if (kk > 72) continue;
            if (kk <= 58) cur[k] = sb[k * 32 + lane];
            else          cur[k] = (c != 7) ? sb[k * 32 + lane] : NEGF;
        }
        __syncwarp();                            // all lanes' LDS done
        if (j + 2 <= 4) { CPTILE(j + 2, (j + 2) % 3, (c == 7) && (j + 2 >= 3)); }

        #pragma unroll
        for (int k = 0; k < 16; ++k) {
            const int kk = 16 * j + k;          // compile-time
            if (kk > 72) continue;
            const float v = cur[k];
            const bool spk = (v >= 0.0f);

            if (kk < 63) {                      // own piece range (pre-update rel)
                const bool newp = spk && (kk > rel);
                const bool was0 = (ns == 0);
                const bool was1 = (ns == 1);
                const bool ge2  = (ns >= 2);
                fm = (newp && was1) ? cm : fm;
                const bool pm = newp && ge2;    // retire an interior piece
                msum += pm ? cm : 0.0f;
                mid0  = pm ? fmaxf(mid0, cm) : mid0;
                // pre-first-spike cm is never consumed; post-first-spike
                // fmaxf(cm, v<0) is a no-op -> spk select unnecessary
                cm = newp ? v : fmaxf(cm, v);
                ns += newp ? 1 : 0;
                if (kk < 10)  tfk = (newp && was0) ? kk : tfk;
                if (kk >= 53) tlk = spk ? kk : tlk;
            }
            rel = spk ? kk + 10 : rel;          // all kk (covers overhang)
            if (kk < 20) relB = spk ? kk + 20 : relB;
            if (kk >= 10) {                     // m0 for s = kk-10
                const float vl = (k >= 10) ? cur[k - 10] : prv[k + 6];
                // kk>=20: relB == rel + 10 (halo influence dead) -> immediate cmp
                const bool un = (kk < 20) ? (kk > relB) : (rel < kk - 10);
                if (un) m0 = fmaxf(m0, vl);
            }
        }
    }
    const float lm = cm;
    if (ns == 1) fm = cm;

    // ---- publish chunk state (overlay onto own ring buffer 0) ----
    float* pub = sbuf[c][0];
    pub[0 * 32 + lane] = __int_as_float(ns);
    pub[1 * 32 + lane] = __int_as_float(t0 + tfk);
    pub[2 * 32 + lane] = __int_as_float(t0 + tlk);
    pub[3 * 32 + lane] = fm;
    pub[4 * 32 + lane] = lm;
    pub[5 * 32 + lane] = mid0;
    pub[6 * 32 + lane] = msum;
    pub[7 * 32 + lane] = m0;
    __syncthreads();

    if (c == 0) {
        float m0g = NEGF;
        #pragma unroll
        for (int cc = 0; cc < 8; ++cc)
            m0g = fmaxf(m0g, sbuf[cc][0][7 * 32 + lane]);

        int nc = 0; float tot = 0.0f;
        float t40 = NEGF, t41 = NEGF, t42 = NEGF, t43 = NEGF;
        bool ov = false, valid = false;
        float open = NEGF; int last_t = -100000;
        #pragma unroll
        for (int cc = 0; cc < 8; ++cc) {
            const float* pc = sbuf[cc][0];
            const int nsc = __float_as_int(pc[0 * 32 + lane]);
            if (nsc == 0) continue;             // spike-free chunk
            const bool conn = (__float_as_int(pc[1 * 32 + lane]) - last_t) <= 10;
            if (conn) {
                open = fmaxf(open, pc[3 * 32 + lane]);
            } else {
                if (valid) { ++nc; tot += open; INS4(open); }
                open = pc[3 * 32 + lane]; valid = true;
            }
            if (nsc >= 2) {
                ++nc; tot += open; INS4(open);  // chain closes inside chunk
                const int mc = nsc - 2;         // interior pieces
                nc += mc; tot += pc[6 * 32 + lane];
                if (mc >= 1) INS4(pc[5 * 32 + lane]);
                if (mc >= 2) ov = true;         // top-4 may be inexact
                open = pc[4 * 32 + lane]; valid = true;
            }
            last_t = __float_as_int(pc[2 * 32 + lane]);
        }
        if (valid) { ++nc; tot += open; INS4(open); }

        float contrib = 0.0f;
        const int label = labels[neuron];
        if (label > nc) {
            const bool any_un = (m0g > -1.0e29f);
            if (!any_un) {
                // full0 => everything masked => spikes exist => global max is
                // the largest cluster max == t40 (non-spikes are < 0 <= spikes)
                contrib = t40;
            } else {
                float m_rest;
                if (nc > 0) {
                    m_rest = m0g;     // argmax is a spike -> mask2 == mask
                } else {
                    int tm = 0; float vm = NEGF;   // cold: no spikes at all
                    for (int t = 0; t < 500; ++t) {
                        const float v = __ldg(p + t * 128);
                        if (v > vm) { vm = v; tm = t; }
                    }
                    float v2 = NEGF;
                    for (int t = 0; t < 500; ++t)
                        if (t < tm - 5 || t > tm + 5)
                            v2 = fmaxf(v2, __ldg(p + t * 128));
                    const bool full2 = (tm <= 5) && (tm + 5 >= 499);
                    m_rest = full2 ? vm : v2;
                }
                const float dE = (float)(label - nc);
                contrib = -((m0g + (dE - 1.0f) * m_rest) / dE);
            }
        } else if (label < nc) {
            if (ov && label >= 1) {
                // rare exact top-4 recompute (serial rescan; t0 == 0 here)
                t40 = t41 = t42 = t43 = NEGF;
                int last = -1000; float cmx = NEGF; bool open2 = false;
                for (int t = 0; t < 500; ++t) {
                    const float v = __ldg(p + t * 128);
                    if (v >= 0.0f) {
                        if (t - last > 10) {
                            if (open2) INS4(cmx);
                            cmx = v; open2 = true;
                        } else cmx = fmaxf(cmx, v);
                        last = t;
                    }
                }
                if (open2) INS4(cmx);
            }
            float s = tot;                      // sum of (nc-label) smallest
            if (label >= 1) s -= t40;
            if (label >= 2) s -= t41;
            if (label >= 3) s -= t42;
            if (label >= 4) s -= t43;
            contrib = s / (float)(nc - label);
        }
        out[1 + neuron] = (float)nc;            // coalesced store

        float val = contrib;
        #pragma unroll
        for (int off = 16; off > 0; off >>= 1)
            val += __shfl_down_sync(0xffffffffu, val, off);
        if (lane == 0) atomicAdd(out, val);
    }
}

extern "C" void kernel_launch(void* const* d_in, const int* in_sizes, int n_in,
                              void* d_out, int out_size) {
    const float* vmem   = (const float*)d_in[0];
    const int*   labels = (const int*)d_in[2];
    float* out = (float*)d_out;

    atca_zero<<<1, 1>>>(out);
    // 32768 neurons / 32 per block = 1024 blocks of 256 (8 chunk-warps)
    atca12<<<1024, 256>>>(vmem, labels, out);
}